// round 9
// baseline (speedup 1.0000x reference)
#include <cuda_runtime.h>
#include <cstdint>
#include <cstddef>

#define C_DIM 256
#define H_DIM 96
#define W_DIM 96
#define TW 16
#define TH 8
#define NPAIR 2
#define RAD 4
#define CC 8
#define NSTAGE (C_DIM / CC)                  // 32
#define S1_STRIDE 24
#define S2_STRIDE 24
#define S2_ROWS (TH + 8)                     // 16
#define S1_WORDS (CC * TH * S1_STRIDE)       // 1536
#define S2_WORDS (CC * S2_ROWS * S2_STRIDE)  // 3072
#define STAGE_WORDS (S1_WORDS + S2_WORDS)    // 4608
#define STAGE_BYTES (STAGE_WORDS * 4)        // 18432
#define NBUF 3
#define NTHREADS 288
#define CADV (CC * H_DIM * W_DIM)            // channel advance per stage (floats)

typedef unsigned long long u64;

union F2U { float2 f2; u64 u; };

__device__ __forceinline__ void fma2(u64 &d, u64 a, u64 b) {
    asm("fma.rn.f32x2 %0, %1, %2, %0;" : "+l"(d) : "l"(a), "l"(b));
}
__device__ __forceinline__ void cp16(uint32_t s, const float* g, uint32_t vbit) {
    int sz = vbit ? 16 : 0;
    asm volatile("cp.async.cg.shared.global [%0], [%1], 16, %2;\n"
                 :: "r"(s), "l"(g), "r"(sz));
}

__global__ __launch_bounds__(NTHREADS, 3)
void corr_kernel(const float* __restrict__ in1, const float* __restrict__ in2,
                 float* __restrict__ out) {
    extern __shared__ float smem[];
    const int tid = threadIdx.x;
    const int w0 = blockIdx.x * TW;
    const int h0 = blockIdx.y * TH;
    const int b  = blockIdx.z;

    const int ph   = tid >> 5;          // warp id = displacement row 0..8
    const int lane = tid & 31;
    const int pc   = lane & 3;          // 4-px block 0..3
    const int r    = lane >> 2;         // tile row 0..7
    const int x0   = pc * 4;

    // ---- hoisted load addressing: threads 0..255 load; 1 in1 chunk + 3 in2 chunks ----
    const bool loader = (tid < 256);
    const float* p1 = in1;
    const float* p2 = in2;
    uint32_t d1 = 0, d2 = 0, mask = 0;
    if (loader) {
        // in1: 16B chunk
        const int c1   = tid >> 5;            // 0..7
        const int rem  = tid & 31;
        const int row1 = rem >> 2;            // 0..7
        const int ch4  = rem & 3;             // 0..3
        p1 = in1 + (((size_t)(b * C_DIM + c1) * H_DIM + (h0 + row1)) * W_DIM + w0 + ch4 * 4);
        d1 = (uint32_t)(((c1 * TH + row1) * S1_STRIDE + ch4 * 4) * 4);

        // in2: half of one 24-float halo row (12 floats = 3 chunks)
        const int rid  = tid >> 1;            // 0..127
        const int c2   = rid >> 4;            // 0..7
        const int row2 = rid & 15;            // 0..15
        const int half = tid & 1;
        const int h2   = h0 + row2 - RAD;
        const int wst  = w0 - RAD + half * 12;
        const bool hv  = (h2 >= 0) && (h2 < H_DIM);
#pragma unroll
        for (int j = 0; j < 3; j++) {
            int w2 = wst + j * 4;
            if (hv && w2 >= 0 && w2 + 4 <= W_DIM) mask |= (1u << j);
        }
        p2 = in2 + (((size_t)(b * C_DIM + c2) * H_DIM + (hv ? h2 : 0)) * W_DIM + wst);
        d2 = (uint32_t)((S1_WORDS + (c2 * S2_ROWS + row2) * S2_STRIDE + half * 12) * 4);
    }

    u64 accE[NPAIR][5];
    float accO[NPAIR][4][2];
#pragma unroll
    for (int k = 0; k < NPAIR; k++) {
#pragma unroll
        for (int d = 0; d < 5; d++) accE[k][d] = 0ull;
#pragma unroll
        for (int d = 0; d < 4; d++) { accO[k][d][0] = 0.f; accO[k][d][1] = 0.f; }
    }

    const uint32_t sb0 = (uint32_t)__cvta_generic_to_shared(smem);

    auto load_stage = [&](int buf) {
        if (loader) {
            const uint32_t sbase = sb0 + (uint32_t)(buf * STAGE_BYTES);
            cp16(sbase + d1, p1, 1u);
#pragma unroll
            for (int j = 0; j < 3; j++)
                cp16(sbase + d2 + j * 16, p2 + j * 4, (mask >> j) & 1u);
            p1 += CADV;
            p2 += CADV;
        }
        asm volatile("cp.async.commit_group;\n");
    };

    load_stage(0);
    load_stage(1);

    int bufc = 0;
    int bufl = 2;
    for (int s = 0; s < NSTAGE; s++) {
        if (s < NSTAGE - 1) {
            asm volatile("cp.async.wait_group 1;\n");
        } else {
            asm volatile("cp.async.wait_group 0;\n");
        }
        __syncthreads();
        if (s + 2 < NSTAGE) load_stage(bufl);

        const float* s1p = smem + bufc * STAGE_WORDS;
        const float* s2p = s1p + S1_WORDS;
#pragma unroll
        for (int cc = 0; cc < CC; cc++) {
            // in1: 2 aligned pairs (LDS.64, conflict-free)
            const float2* v1row = (const float2*)(s1p + (cc * TH + r) * S1_STRIDE + x0);
            F2U v1[NPAIR];
#pragma unroll
            for (int q = 0; q < NPAIR; q++) v1[q].f2 = v1row[q];

            // in2: 12-float span as 6 aligned pairs
            const float2* v2row = (const float2*)(s2p + (cc * S2_ROWS + (r + ph)) * S2_STRIDE + x0);
            F2U v2[6];
#pragma unroll
            for (int q = 0; q < 6; q++) v2[q].f2 = v2row[q];

            // even dw: packed FMA
#pragma unroll
            for (int k = 0; k < NPAIR; k++)
#pragma unroll
                for (int dh = 0; dh < 5; dh++)
                    fma2(accE[k][dh], v1[k].u, v2[k + dh].u);

            // odd dw: scalar FMAs on named halves
#pragma unroll
            for (int k = 0; k < NPAIR; k++)
#pragma unroll
                for (int dh = 0; dh < 4; dh++) {
                    accO[k][dh][0] = __fmaf_rn(v1[k].f2.x, v2[k + dh].f2.y, accO[k][dh][0]);
                    accO[k][dh][1] = __fmaf_rn(v1[k].f2.y, v2[k + dh + 1].f2.x, accO[k][dh][1]);
                }
        }

        bufc = (bufc == NBUF - 1) ? 0 : bufc + 1;
        bufl = (bufl == NBUF - 1) ? 0 : bufl + 1;
    }

    // epilogue
    const size_t plane = (size_t)H_DIM * W_DIM;
    float* op = out + (size_t)(b * 81 + ph * 9) * plane +
                (size_t)(h0 + r) * W_DIM + (w0 + x0);
#pragma unroll
    for (int dh = 0; dh < 5; dh++) {
        u64* orow = (u64*)(op + (size_t)(2 * dh) * plane);
#pragma unroll
        for (int k = 0; k < NPAIR; k++) orow[k] = accE[k][dh];
    }
#pragma unroll
    for (int dh = 0; dh < 4; dh++) {
        float* orow = op + (size_t)(2 * dh + 1) * plane;
#pragma unroll
        for (int k = 0; k < NPAIR; k++) {
            F2U t; t.f2.x = accO[k][dh][0]; t.f2.y = accO[k][dh][1];
            *(u64*)(orow + 2 * k) = t.u;
        }
    }
}

extern "C" void kernel_launch(void* const* d_in, const int* in_sizes, int n_in,
                              void* d_out, int out_size) {
    const float* in1 = (const float*)d_in[0];
    const float* in2 = (const float*)d_in[1];
    float* out = (float*)d_out;
    int Bn = in_sizes[0] / (C_DIM * H_DIM * W_DIM);
    size_t smem_bytes = (size_t)NBUF * STAGE_BYTES;  // 55296
    cudaFuncSetAttribute(corr_kernel, cudaFuncAttributeMaxDynamicSharedMemorySize,
                         (int)smem_bytes);
    dim3 grid(W_DIM / TW, H_DIM / TH, Bn);
    corr_kernel<<<grid, NTHREADS, smem_bytes>>>(in1, in2, out);
}